// round 9
// baseline (speedup 1.0000x reference)
#include <cuda_runtime.h>

#define CH 64
#define MMAX 50000
#define CAP 80
#define OVF_MAX 8192
#define TILE_M 32

// Allocation-free scratch. Zero-initialized at module load; kernels restore
// the zero invariant each run (seg re-zeroes g_cnt, final re-zeroes g_ovf_n).
__device__ float4 g_S4[MMAX * (CH / 4)];   // segment sums [M][64]
__device__ float  g_deg[MMAX];
__device__ int    g_cnt[MMAX];
__device__ int2   g_bin[MMAX * CAP];       // {src, __float_as_int(ew)}
__device__ int    g_ovf_n;
__device__ int2   g_ovf[OVF_MAX];          // {dst, src}
__device__ float  g_ovf_w[OVF_MAX];

#define FFMA2(acc, a, b) \
    asm("fma.rn.f32x2 %0, %1, %2, %0;" : "+l"(acc) : "l"(a), "l"(b))

#define CP_ASYNC16(saddr, gptr) \
    asm volatile("cp.async.cg.shared.global [%0], [%1], 16;" \
                 :: "r"(saddr), "l"(gptr))

// 4 edges/thread, 4 independent atomic chains in flight (MLP=4).
__global__ void fill_kernel(const int* __restrict__ idx,
                            const int* __restrict__ idx1,
                            const float* __restrict__ ew,
                            int E) {
    int t = blockIdx.x * blockDim.x + threadIdx.x;
    int base = t * 4;
    if (base >= E) return;
    if (base + 3 < E) {
        int4   ss = __ldg((const int4*)idx + t);
        int4   dd = __ldg((const int4*)idx1 + t);
        float4 ww = __ldg((const float4*)ew + t);
        int s0 = atomicAdd(&g_cnt[dd.x], 1);
        int s1 = atomicAdd(&g_cnt[dd.y], 1);
        int s2 = atomicAdd(&g_cnt[dd.z], 1);
        int s3 = atomicAdd(&g_cnt[dd.w], 1);
        int srcs[4] = {ss.x, ss.y, ss.z, ss.w};
        int dsts[4] = {dd.x, dd.y, dd.z, dd.w};
        int slots[4] = {s0, s1, s2, s3};
        float ws[4] = {ww.x, ww.y, ww.z, ww.w};
        #pragma unroll
        for (int j = 0; j < 4; j++) {
            if (slots[j] < CAP) {
                g_bin[dsts[j] * CAP + slots[j]] =
                    make_int2(srcs[j], __float_as_int(ws[j]));
            } else {
                int o = atomicAdd(&g_ovf_n, 1);
                if (o < OVF_MAX) {
                    g_ovf[o] = make_int2(dsts[j], srcs[j]);
                    g_ovf_w[o] = ws[j];
                }
            }
        }
    } else {
        for (int e = base; e < E; e++) {
            int dst = idx1[e];
            int slot = atomicAdd(&g_cnt[dst], 1);
            if (slot < CAP) {
                g_bin[dst * CAP + slot] = make_int2(idx[e], __float_as_int(ew[e]));
            } else {
                int o = atomicAdd(&g_ovf_n, 1);
                if (o < OVF_MAX) {
                    g_ovf[o] = make_int2(dst, idx[e]);
                    g_ovf_w[o] = ew[e];
                }
            }
        }
    }
}

// One warp per segment, 2 edges per iteration (lanes 0-15: even edge via
// float4, lanes 16-31: odd edge). Plain stores, no atomics, no pre-zero.
// Re-zeroes g_cnt[w] for the next replay. Overflow applied inline.
__global__ __launch_bounds__(256) void seg_kernel(const float4* __restrict__ A4,
                                                  int M) {
    int w = (blockIdx.x * blockDim.x + threadIdx.x) >> 5;
    int l = threadIdx.x & 31;
    if (w >= M) return;
    int cntRaw = g_cnt[w];
    if (l == 0) g_cnt[w] = 0;
    int cnt = (cntRaw > CAP) ? CAP : cntRaw;
    int half = l >> 4;   // 0: even-indexed edges, 1: odd
    int q = l & 15;

    float4 acc = make_float4(0.f, 0.f, 0.f, 0.f);
    float dl = 0.f;
    for (int c0 = 0; c0 < cnt; c0 += 32) {
        int nn = cnt - c0; if (nn > 32) nn = 32;
        int2 b = (l < nn) ? __ldg(&g_bin[w * CAP + c0 + l]) : make_int2(0, 0);
        if (l < nn) dl += __int_as_float(b.y);
        for (int j = 0; j < nn; j += 2) {
            int srcA = __shfl_sync(0xffffffffu, b.x, j);
            int srcB = __shfl_sync(0xffffffffu, b.x, j + 1);  // 0 if j+1>=nn
            int src = half ? srcB : srcA;
            bool act = half ? (j + 1 < nn) : true;
            if (act) {
                float4 v = __ldg(&A4[src * 16 + q]);
                acc.x += v.x; acc.y += v.y; acc.z += v.z; acc.w += v.w;
            }
        }
    }

    // Overflow list (normally empty: one broadcast LDG).
    int novf = g_ovf_n;
    if (novf > OVF_MAX) novf = OVF_MAX;
    for (int i = 0; i < novf; i++) {
        int2 ds = __ldg(&g_ovf[i]);
        if (ds.x == w) {
            if (half == 0) {
                float4 v = __ldg(&A4[ds.y * 16 + q]);
                acc.x += v.x; acc.y += v.y; acc.z += v.z; acc.w += v.w;
            }
            if (l == 0) dl += g_ovf_w[i];
        }
    }

    acc.x += __shfl_xor_sync(0xffffffffu, acc.x, 16);
    acc.y += __shfl_xor_sync(0xffffffffu, acc.y, 16);
    acc.z += __shfl_xor_sync(0xffffffffu, acc.z, 16);
    acc.w += __shfl_xor_sync(0xffffffffu, acc.w, 16);
    #pragma unroll
    for (int o = 16; o; o >>= 1) dl += __shfl_xor_sync(0xffffffffu, dl, o);

    if (l < 16) g_S4[w * 16 + q] = acc;
    if (l == 0) g_deg[w] = dl;
}

// Epilogue: out[m,c] = deg*(x·W1[c]+b1[c]) + S·Wt[:,c] + x·W2[c] + b2[c].
// Weights resident in smem for the whole block; X/S tiles double-buffered
// via cp.async.cg so the gather latency of tile t+1 hides under tile t's FMAs.
__global__ __launch_bounds__(256) void final_kernel(
        const float4* __restrict__ A4,
        const int* __restrict__ vn,
        const float* __restrict__ W1,
        const float* __restrict__ b1,
        const float* __restrict__ W2,
        const float* __restrict__ b2,
        const float* __restrict__ Wt,   // weight, layout [k][c]
        float* __restrict__ out,
        int M, int numTiles) {
    extern __shared__ float4 sm[];
    float4* sW1v = sm;                   // [16][64]
    float4* sW2v = sm + 1024;            // [16][64]
    float4* sWv  = sm + 2048;            // [16][64]
    float4* sBuf = sm + 3072;            // 2 x (X[512] | S[512])

    int tid = threadIdx.x;
    int c = tid & 63;
    int g = tid >> 6;
    float b1c = __ldg(&b1[c]);
    float b2c = __ldg(&b2[c]);

    if (blockIdx.x == 0 && tid == 0) g_ovf_n = 0;   // reset for next replay

    const float4* W1v4 = (const float4*)W1;
    const float4* W2v4 = (const float4*)W2;
    for (int i = tid; i < 1024; i += 256) {
        int kk = i >> 6, cc = i & 63;
        sW1v[i] = __ldg(&W1v4[cc * 16 + kk]);
        sW2v[i] = __ldg(&W2v4[cc * 16 + kk]);
        int k0 = kk * 4;
        sWv[i] = make_float4(__ldg(&Wt[(k0 + 0) * CH + cc]),
                             __ldg(&Wt[(k0 + 1) * CH + cc]),
                             __ldg(&Wt[(k0 + 2) * CH + cc]),
                             __ldg(&Wt[(k0 + 3) * CH + cc]));
    }

    auto stage = [&](int tile, int buf) {
        float4* bX = sBuf + buf * 1024;
        float4* bS = bX + 512;
        int m0 = tile * TILE_M;
        for (int i = tid; i < TILE_M * 16; i += 256) {
            int r = i >> 4, q = i & 15;
            int m = m0 + r;
            int mc = (m < M) ? m : 0;
            int rowA = (m < M) ? vn[m] : 0;
            unsigned sx = (unsigned)__cvta_generic_to_shared(bX + i);
            unsigned ss = (unsigned)__cvta_generic_to_shared(bS + i);
            CP_ASYNC16(sx, &A4[rowA * 16 + q]);
            CP_ASYNC16(ss, &g_S4[mc * 16 + q]);
        }
    };

    int t0 = blockIdx.x;
    if (t0 >= numTiles) return;
    stage(t0, 0);
    asm volatile("cp.async.commit_group;" ::: "memory");

    int bufc = 0;
    for (int tile = t0; tile < numTiles; tile += gridDim.x) {
        int nt = tile + gridDim.x;
        if (nt >= numTiles) nt = tile;   // clamped dummy prefetch (uniform)
        stage(nt, bufc ^ 1);
        asm volatile("cp.async.commit_group;" ::: "memory");
        asm volatile("cp.async.wait_group 1;" ::: "memory");
        __syncthreads();

        float4* bX = sBuf + bufc * 1024;
        float4* bS = bX + 512;
        int m0 = tile * TILE_M;

        unsigned long long a1[8], a2[8], a3[8];
        #pragma unroll
        for (int r = 0; r < 8; r++) { a1[r] = 0ull; a2[r] = 0ull; a3[r] = 0ull; }

        #pragma unroll
        for (int kk = 0; kk < 16; kk++) {
            ulonglong2 w1 = *(const ulonglong2*)&sW1v[kk * 64 + c];
            ulonglong2 w2 = *(const ulonglong2*)&sW2v[kk * 64 + c];
            ulonglong2 wv = *(const ulonglong2*)&sWv [kk * 64 + c];
            #pragma unroll
            for (int r = 0; r < 8; r++) {
                ulonglong2 x = *(const ulonglong2*)&bX[(g * 8 + r) * 16 + kk];
                ulonglong2 s = *(const ulonglong2*)&bS[(g * 8 + r) * 16 + kk];
                FFMA2(a1[r], x.x, w1.x); FFMA2(a1[r], x.y, w1.y);
                FFMA2(a2[r], x.x, w2.x); FFMA2(a2[r], x.y, w2.y);
                FFMA2(a3[r], s.x, wv.x); FFMA2(a3[r], s.y, wv.y);
            }
        }

        #pragma unroll
        for (int r = 0; r < 8; r++) {
            int m = m0 + g * 8 + r;
            if (m < M) {
                unsigned lo, hi;
                float s1, s2, s3;
                asm("mov.b64 {%0,%1}, %2;" : "=r"(lo), "=r"(hi) : "l"(a1[r]));
                s1 = __uint_as_float(lo) + __uint_as_float(hi);
                asm("mov.b64 {%0,%1}, %2;" : "=r"(lo), "=r"(hi) : "l"(a2[r]));
                s2 = __uint_as_float(lo) + __uint_as_float(hi);
                asm("mov.b64 {%0,%1}, %2;" : "=r"(lo), "=r"(hi) : "l"(a3[r]));
                s3 = __uint_as_float(lo) + __uint_as_float(hi);
                float d = __ldg(&g_deg[m]);
                out[m * CH + c] = d * (s1 + b1c) + s3 + s2 + b2c;
            }
        }
        __syncthreads();   // protect bufc before next iteration's stage
        bufc ^= 1;
    }
}

extern "C" void kernel_launch(void* const* d_in, const int* in_sizes, int n_in,
                              void* d_out, int out_size) {
    const float* A    = (const float*)d_in[0];   // [N, 64] f32
    const int*   vn   = (const int*)d_in[1];     // [M] int32
    const int*   idx  = (const int*)d_in[2];     // [E] int32
    const int*   idx1 = (const int*)d_in[3];     // [E] int32
    const float* ew   = (const float*)d_in[4];   // [E] f32
    const float* Wt   = (const float*)d_in[5];   // [64, 64] = [CIN][COUT]
    const float* W1   = (const float*)d_in[6];   // [64, 64] = [COUT][CIN]
    const float* b1   = (const float*)d_in[7];   // [64]
    const float* W2   = (const float*)d_in[8];   // [64, 64]
    const float* b2   = (const float*)d_in[9];   // [64]
    float* out = (float*)d_out;

    int M = in_sizes[1];
    int E = in_sizes[2];

    {
        int threads4 = (E + 3) / 4;
        fill_kernel<<<(threads4 + 255) / 256, 256>>>(idx, idx1, ew, E);
    }
    {
        int blocks = (M * 32 + 255) / 256;
        seg_kernel<<<blocks, 256>>>((const float4*)A, M);
    }
    {
        int smemBytes = 5120 * sizeof(float4);   // 81920
        cudaFuncSetAttribute(final_kernel,
                             cudaFuncAttributeMaxDynamicSharedMemorySize,
                             smemBytes);
        int numTiles = (M + TILE_M - 1) / TILE_M;
        int blocks = 296;                         // 2 blocks/SM on 148 SMs
        if (blocks > numTiles) blocks = numTiles;
        final_kernel<<<blocks, 256, smemBytes>>>(
            (const float4*)A, vn, W1, b1, W2, b2, Wt, out, M, numTiles);
    }
}